// round 16
// baseline (speedup 1.0000x reference)
#include <cuda_runtime.h>
#include <cuda_fp16.h>
#include <cstdint>

#define NN 50000
#define NE 600000
#define HID 128
#define TILE_M 128
#define GBLK ((NN + TILE_M - 1) / TILE_M)

// ---------------- scratch (static device globals; no allocations) ------------
__device__ int   g_deg[NN];
__device__ int   g_rowptr[NN];
__device__ int   g_cursor[NN];
__device__ float g_inv[NN];
__device__ int   g_col[NE];
__device__ int   g_bsums[64];
// fp16 operand buffers: A-side hi only; W-side hi+lo. h lives as fp16 ONLY.
__device__ __half g_xhi[(size_t)NN * HID];
__device__ __half g_h1hi[(size_t)NN * HID];
__device__ __half g_h2hi[(size_t)NN * HID];
__device__ __half g_whi[6 * HID * HID], g_wlo[6 * HID * HID];

// ---------------- helpers ----------------------------------------------------
__device__ __forceinline__ uint32_t smem_u32(const void* p) {
    uint32_t a;
    asm("{ .reg .u64 t; cvta.to.shared.u64 t, %1; cvt.u32.u64 %0, t; }"
        : "=r"(a) : "l"(p));
    return a;
}

#define SWZ(o) ((o) ^ (((o) >> 3) & 0x70))

__device__ __forceinline__ void ldsm4(uint32_t* r, uint32_t addr) {
    asm volatile("ldmatrix.sync.aligned.m8n8.x4.shared.b16 {%0,%1,%2,%3}, [%4];"
                 : "=r"(r[0]), "=r"(r[1]), "=r"(r[2]), "=r"(r[3]) : "r"(addr));
}

__device__ __forceinline__ void mma_f16(float* c, const uint32_t* a,
                                        const uint32_t* b) {
    asm volatile(
        "mma.sync.aligned.m16n8k16.row.col.f32.f16.f16.f32 "
        "{%0,%1,%2,%3}, {%4,%5,%6,%7}, {%8,%9}, {%0,%1,%2,%3};"
        : "+f"(c[0]), "+f"(c[1]), "+f"(c[2]), "+f"(c[3])
        : "r"(a[0]), "r"(a[1]), "r"(a[2]), "r"(a[3]), "r"(b[0]), "r"(b[1]));
}

__device__ __forceinline__ void cp16(uint32_t dst, const void* src, uint32_t n) {
    asm volatile("cp.async.cg.shared.global [%0], [%1], 16, %2;"
                 :: "r"(dst), "l"(src), "r"(n) : "memory");
}
__device__ __forceinline__ void cp_commit_wait() {
    asm volatile("cp.async.commit_group;" ::: "memory");
    asm volatile("cp.async.wait_group 0;" ::: "memory");
}

__device__ __forceinline__ uint32_t pack_h2(__half a, __half b) {
    __half2 t = __halves2half2(a, b);
    return *(uint32_t*)&t;
}

__device__ __forceinline__ void split_h(float v, __half& h, __half& l) {
    h = __float2half_rn(v);
    l = __float2half_rn(v - __half2float(h));
}

// int64-vs-int32 probe on first 64 src entries (block-uniform, <=512B reads)
__device__ __forceinline__ int probe64(const void* p) {
    const long long* q = (const long long*)p;
    for (int e = 0; e < 64; e++) {
        long long v = q[e];
        if (v < 0 || v >= NN) return 0;
    }
    return 1;
}

__device__ __forceinline__ int edge_val(const void* ei, int is64, int idx) {
    if (is64) return (int)((const long long*)ei)[idx];
    return ((const int*)ei)[idx];
}

// ---------------- CSR build --------------------------------------------------
__global__ void k_zero_deg() {
    int i = blockIdx.x * blockDim.x + threadIdx.x;
    if (i < NN) g_deg[i] = 0;
}

__global__ void k_count(const void* __restrict__ ei) {
    __shared__ int s64;
    if (threadIdx.x == 0) s64 = probe64(ei);
    __syncthreads();
    int e = blockIdx.x * blockDim.x + threadIdx.x;
    if (e < NE) {
        int d = edge_val(ei, s64, NE + e);
        if ((unsigned)d < NN) atomicAdd(&g_deg[d], 1);
    }
}

__global__ void k_scan1() {
    __shared__ int wsum[32];
    int i = blockIdx.x * 1024 + threadIdx.x;
    int lane = threadIdx.x & 31, w = threadIdx.x >> 5;
    int v = (i < NN) ? g_deg[i] : 0;
    int s = v;
#pragma unroll
    for (int o = 1; o < 32; o <<= 1) {
        int t = __shfl_up_sync(0xffffffffu, s, o);
        if (lane >= o) s += t;
    }
    if (lane == 31) wsum[w] = s;
    __syncthreads();
    if (w == 0) {
        int ws = wsum[lane];
#pragma unroll
        for (int o = 1; o < 32; o <<= 1) {
            int t = __shfl_up_sync(0xffffffffu, ws, o);
            if (lane >= o) ws += t;
        }
        wsum[lane] = ws;
    }
    __syncthreads();
    int incl = s + (w > 0 ? wsum[w - 1] : 0);
    if (i < NN) g_rowptr[i] = incl - v;
    if (threadIdx.x == 1023) g_bsums[blockIdx.x] = incl;
}

// scan3 with in-block scan of the (<=64) block sums: no separate k_scan2
__global__ void k_scan3(int nb) {
    __shared__ int sh[64];
    int t = threadIdx.x;
    int v0 = 0;
    if (t < 64) { v0 = (t < nb) ? g_bsums[t] : 0; sh[t] = v0; }
    __syncthreads();
#pragma unroll
    for (int o = 1; o < 64; o <<= 1) {
        int u = (t >= o && t < 64) ? sh[t - o] : 0;
        __syncthreads();
        if (t < 64) sh[t] += u;
        __syncthreads();
    }
    if (t < 64) sh[t] -= v0;      // exclusive
    __syncthreads();
    int i = blockIdx.x * blockDim.x + t;
    if (i < NN) {
        int rp = g_rowptr[i] + sh[i >> 10];
        g_rowptr[i] = rp;
        g_cursor[i] = rp;
        int d = g_deg[i];
        g_inv[i] = 1.0f / (float)(d > 0 ? d : 1);
    }
}

__global__ void k_fill(const void* __restrict__ ei) {
    __shared__ int s64;
    if (threadIdx.x == 0) s64 = probe64(ei);
    __syncthreads();
    int e = blockIdx.x * blockDim.x + threadIdx.x;
    if (e < NE) {
        int s = edge_val(ei, s64, e);
        int d = edge_val(ei, s64, NE + e);
        if ((unsigned)s < NN && (unsigned)d < NN) {
            int pos = atomicAdd(&g_cursor[d], 1);
            if ((unsigned)pos < NE) g_col[pos] = s;
        }
    }
}

// ---------------- pre-convert (merged): W -> fp16 hi/lo; x -> fp16 hi --------
#define WELEMS (6 * HID * HID)
__global__ void k_conv(const float* __restrict__ x,
                       const float* __restrict__ w0, const float* __restrict__ w1,
                       const float* __restrict__ w2, const float* __restrict__ w3,
                       const float* __restrict__ w4, const float* __restrict__ w5) {
    int idx = blockIdx.x * blockDim.x + threadIdx.x;
    if (idx < WELEMS) {
        int m = idx >> 14, off = idx & 16383;
        const float* w = (m == 0) ? w0 : (m == 1) ? w1 : (m == 2) ? w2
                       : (m == 3) ? w3 : (m == 4) ? w4 : w5;
        __half h, l;
        split_h(w[off], h, l);
        g_whi[idx] = h; g_wlo[idx] = l;
    } else {
        int q = idx - WELEMS;                       // one float4 of x per thread
        if ((size_t)q * 4 < (size_t)NN * HID) {
            float4 v = *(const float4*)(x + (size_t)q * 4);
            *(uint2*)(g_xhi + (size_t)q * 4) = make_uint2(
                pack_h2(__float2half_rn(v.x), __float2half_rn(v.y)),
                pack_h2(__float2half_rn(v.z), __float2half_rn(v.w)));
        }
    }
}

// ---------------- fused agg + mma.sync GEMM ----------------------------------
// Phase 1: gather mean rows for this CTA's 128-row tile straight into smem
//          (two 16KB half-tiles, SW128, fp16) — half-warp per node.
// Phase 2: C += Ahi*Whi + Ahi*Wlo over K=256 (kc 0,1 = mean from smem;
//          kc 2,3 = h/x from global via cp.async), 8 warps 4m x 2n.
#define SM_MEAN 0              // 32KB: [kc0 tile 16KB][kc1 tile 16KB]
#define SM_AHI  32768          // 16KB
#define SM_WHI  49152          // 16KB
#define SM_WLO  65536          // 16KB
#define SM_TOTAL 81920

__global__ void __launch_bounds__(256, 2) k_fused(
    const float* __restrict__ bias, float* __restrict__ out_ext,
    int src_sel, int widx, int dst_sel, int relu)
{
    extern __shared__ char smem[];
    const __half* in = (src_sel == 0) ? g_xhi : (src_sel == 1 ? g_h1hi : g_h2hi);
    __half* ohi = (dst_sel == 1) ? g_h1hi : (dst_sel == 2 ? g_h2hi : (__half*)0);

    uint32_t sb = smem_u32(smem);
    int tid = threadIdx.x;
    int lane = tid & 31, warp = tid >> 5;
    int row0 = blockIdx.x * TILE_M;

    // ---------------- phase 1: mean gather into smem -------------------------
    {
        int half = lane >> 4;        // which node of the pair
        int fl = lane & 15;          // feature lane: 8 halves (uint4) each
#pragma unroll 1
        for (int i = 0; i < 8; i++) {
            int r = warp * 16 + i * 2 + half;
            int node = row0 + r;
            float a0 = 0.f, a1 = 0.f, a2 = 0.f, a3 = 0.f,
                  a4 = 0.f, a5 = 0.f, a6 = 0.f, a7 = 0.f;
            if (node < NN) {
                int s = g_rowptr[node];
                int d = g_deg[node];
                int k = 0;
                for (; k + 4 <= d; k += 4) {
                    uint4 v[4];
#pragma unroll
                    for (int u = 0; u < 4; u++) {
                        int j = g_col[s + k + u];
                        v[u] = __ldg((const uint4*)(in + (size_t)j * HID) + fl);
                    }
#pragma unroll
                    for (int u = 0; u < 4; u++) {
                        float2 p0 = __half22float2(*(__half2*)&v[u].x);
                        float2 p1 = __half22float2(*(__half2*)&v[u].y);
                        float2 p2 = __half22float2(*(__half2*)&v[u].z);
                        float2 p3 = __half22float2(*(__half2*)&v[u].w);
                        a0 += p0.x; a1 += p0.y; a2 += p1.x; a3 += p1.y;
                        a4 += p2.x; a5 += p2.y; a6 += p3.x; a7 += p3.y;
                    }
                }
                for (; k < d; k++) {
                    int j = g_col[s + k];
                    uint4 v = __ldg((const uint4*)(in + (size_t)j * HID) + fl);
                    float2 p0 = __half22float2(*(__half2*)&v.x);
                    float2 p1 = __half22float2(*(__half2*)&v.y);
                    float2 p2 = __half22float2(*(__half2*)&v.z);
                    float2 p3 = __half22float2(*(__half2*)&v.w);
                    a0 += p0.x; a1 += p0.y; a2 += p1.x; a3 += p1.y;
                    a4 += p2.x; a5 += p2.y; a6 += p3.x; a7 += p3.y;
                }
                float inv = g_inv[node];
                a0 *= inv; a1 *= inv; a2 *= inv; a3 *= inv;
                a4 *= inv; a5 *= inv; a6 *= inv; a7 *= inv;
            }
            uint4 pk;
            pk.x = pack_h2(__float2half_rn(a0), __float2half_rn(a1));
            pk.y = pack_h2(__float2half_rn(a2), __float2half_rn(a3));
            pk.z = pack_h2(__float2half_rn(a4), __float2half_rn(a5));
            pk.w = pack_h2(__float2half_rn(a6), __float2half_rn(a7));
            // features fl*8..fl*8+7: fl<8 -> kc0 tile, fl>=8 -> kc1 tile
            uint32_t doff = SWZ((uint32_t)(r * 128 + (fl & 7) * 16)) +
                            (uint32_t)(fl >> 3) * 16384u;
            *(uint4*)(smem + SM_MEAN + doff) = pk;
        }
    }
    __syncthreads();

    // ---------------- phase 2: MMA over K=256 --------------------------------
    float acc[2][8][4];
#pragma unroll
    for (int mt = 0; mt < 2; mt++)
#pragma unroll
        for (int nt = 0; nt < 8; nt++)
#pragma unroll
            for (int q = 0; q < 4; q++) acc[mt][nt][q] = 0.f;

    int wm = warp & 3, wn = warp >> 2;
    int l15 = lane & 15, lhi = lane >> 4;
    int bn = ((lane >> 4) << 3) + (lane & 7);
    int bk = ((lane >> 3) & 1) * 16;
    int fr = tid >> 1;            // fill row 0..127
    int fh = tid & 1;             // fill half (64-byte granule)

    for (int kc = 0; kc < 4; kc++) {
        const __half *Wh, *Wl;
        if (kc < 2) {
            Wh = g_whi + (size_t)(2 * widx) * HID * HID;
            Wl = g_wlo + (size_t)(2 * widx) * HID * HID;
        } else {
            Wh = g_whi + (size_t)(2 * widx + 1) * HID * HID;
            Wl = g_wlo + (size_t)(2 * widx + 1) * HID * HID;
        }
        int koff = (kc & 1) * 64;

        // fill: W always; A only for kc>=2 (kc 0/1 read the smem mean tiles)
        {
            size_t wbase = (size_t)fr * HID + koff + fh * 32;
#pragma unroll
            for (int i = 0; i < 4; i++) {
                uint32_t dof = SWZ((uint32_t)(fr * 128 + fh * 64 + i * 16));
                cp16(sb + SM_WHI + dof, Wh + wbase + i * 8, 16u);
                cp16(sb + SM_WLO + dof, Wl + wbase + i * 8, 16u);
            }
            if (kc >= 2) {
                int grow = row0 + fr;
                uint32_t aok = (grow < NN) ? 16u : 0u;
                size_t abase = (size_t)grow * HID + koff + fh * 32;
#pragma unroll
                for (int i = 0; i < 4; i++) {
                    uint32_t dof = SWZ((uint32_t)(fr * 128 + fh * 64 + i * 16));
                    cp16(sb + SM_AHI + dof, in + abase + i * 8, aok);
                }
            }
        }
        cp_commit_wait();
        __syncthreads();

        uint32_t abase_s = (kc == 0) ? (uint32_t)SM_MEAN
                         : (kc == 1) ? (uint32_t)(SM_MEAN + 16384)
                                     : (uint32_t)SM_AHI;
#pragma unroll
        for (int ks = 0; ks < 4; ks++) {
            int kb2 = ks * 32;
            uint32_t a_hi[2][4];
#pragma unroll
            for (int mt = 0; mt < 2; mt++) {
                uint32_t so = SWZ((uint32_t)((wm * 32 + mt * 16 + l15) * 128 +
                                             kb2 + lhi * 16));
                ldsm4(a_hi[mt], sb + abase_s + so);
            }
#pragma unroll
            for (int g = 0; g < 4; g++) {
                uint32_t so = SWZ((uint32_t)((wn * 64 + g * 16 + bn) * 128 +
                                             kb2 + bk));
                uint32_t bh[4], bl[4];
                ldsm4(bh, sb + SM_WHI + so);
                ldsm4(bl, sb + SM_WLO + so);
#pragma unroll
                for (int mt = 0; mt < 2; mt++)
#pragma unroll
                    for (int sub = 0; sub < 2; sub++) {
                        float* c = acc[mt][g * 2 + sub];
                        mma_f16(c, a_hi[mt], bh + sub * 2);
                        mma_f16(c, a_hi[mt], bl + sub * 2);
                    }
            }
        }
        __syncthreads();
    }

    // ---- epilogue: bias + opt relu; fp16 store for h, fp32 for final --------
#pragma unroll
    for (int nt = 0; nt < 8; nt++) {
        int col = wn * 64 + nt * 8 + (lane & 3) * 2;
        float bx = __ldg(bias + col);
        float by = __ldg(bias + col + 1);
#pragma unroll
        for (int mt = 0; mt < 2; mt++) {
            int rbase = row0 + wm * 32 + mt * 16 + (lane >> 2);
            float* c = acc[mt][nt];
#pragma unroll
            for (int half_i = 0; half_i < 2; half_i++) {
                int r = rbase + half_i * 8;
                if (r >= NN) continue;
                float2 o = make_float2(c[half_i * 2 + 0] + bx,
                                       c[half_i * 2 + 1] + by);
                if (relu) { o.x = fmaxf(o.x, 0.f); o.y = fmaxf(o.y, 0.f); }
                size_t off = (size_t)r * HID + col;
                if (ohi)
                    *(uint32_t*)(ohi + off) =
                        pack_h2(__float2half_rn(o.x), __float2half_rn(o.y));
                else
                    *(float2*)(out_ext + off) = o;
            }
        }
    }
}

// ---------------- launch -----------------------------------------------------
extern "C" void kernel_launch(void* const* d_in, const int* in_sizes, int n_in,
                              void* d_out, int out_size) {
    const float* x   = (const float*)d_in[0];
    const void*  ei  = d_in[1];
    const float* Wl1 = (const float*)d_in[2];
    const float* Wr1 = (const float*)d_in[3];
    const float* b1  = (const float*)d_in[4];
    const float* Wl2 = (const float*)d_in[5];
    const float* Wr2 = (const float*)d_in[6];
    const float* b2  = (const float*)d_in[7];
    const float* Wl3 = (const float*)d_in[8];
    const float* Wr3 = (const float*)d_in[9];
    const float* b3  = (const float*)d_in[10];
    float* out = (float*)d_out;

    cudaFuncSetAttribute(k_fused, cudaFuncAttributeMaxDynamicSharedMemorySize,
                         SM_TOTAL);

    // CSR build + operand pre-conversion
    k_zero_deg<<<(NN + 255) / 256, 256>>>();
    k_count<<<(NE + 255) / 256, 256>>>(ei);
    int nb = (NN + 1023) / 1024;
    k_scan1<<<nb, 1024>>>();
    k_scan3<<<(NN + 255) / 256, 256>>>(nb);
    k_fill<<<(NE + 255) / 256, 256>>>(ei);
    int cthreads = WELEMS + NN * HID / 4;
    k_conv<<<(cthreads + 255) / 256, 256>>>(x, Wl1, Wr1, b1 ? Wl2 : Wl2, Wr2,
                                            Wl3, Wr3);

    // 3 fused layers
    k_fused<<<GBLK, 256, SM_TOTAL>>>(b1, out, 0, 0, 1, 1);
    k_fused<<<GBLK, 256, SM_TOTAL>>>(b2, out, 1, 1, 2, 0);
    k_fused<<<GBLK, 256, SM_TOTAL>>>(b3, out, 2, 2, 3, 0);
}